// round 3
// baseline (speedup 1.0000x reference)
#include <cuda_runtime.h>

#define HH 512
#define WW 512
#define NC 48
#define NP (HH*WW)
#define NQ 12  // 48 floats = 12 float4

// ---- scratch (static device globals: allocation-free, graph-safe) ----
// planar layout: plane c at g_a[c*NP + p]
__device__ float g_a[NC*NP];
__device__ float g_b[NC*NP];
__device__ float g_s0[NP];    // s buffer paired with g_a
__device__ float g_s1[NP];    // s buffer paired with g_b
__device__ float g_aux[12*NP];   // 12 planar coefficient planes

// ---- K0: per-pixel stencil weights from Dt (periodic rolls), folded /dg, 0.5*hinv,
//          and zero-pad masks. Written PLANAR for coalesced reads in k_step. ----
__global__ void k_aux(const float* __restrict__ Dt, const float* __restrict__ dg,
                      const float* __restrict__ hinv) {
    int p = blockIdx.x * blockDim.x + threadIdx.x;
    if (p >= NP) return;
    int h = p >> 9, w = p & 511;
    int hm = (h - 1) & 511, hp = (h + 1) & 511;
    int wm = (w - 1) & 511, wp = (w + 1) & 511;
    // Dt split: comp0 = a, comp1 = c, comp2 = b
    #define DTA(hh,ww) Dt[(((hh)<<9)+(ww))*3+0]
    #define DTC(hh,ww) Dt[(((hh)<<9)+(ww))*3+1]
    #define DTB(hh,ww) Dt[(((hh)<<9)+(ww))*3+2]
    float a00 = DTA(h,w),  c00 = DTC(h,w),  b00 = DTB(h,w);
    float a_hm = DTA(hm,w), b_hm = DTB(hm,w);
    float a_hp = DTA(hp,w), b_hp = DTB(hp,w);
    float c_wm = DTC(h,wm), b_wm = DTB(h,wm);
    float c_wp = DTC(h,wp), b_wp = DTB(h,wp);
    float b_mm = DTB(hm,wm);
    float b_mp = DTB(hm,wp);
    float b_pm = DTB(hp,wm);
    float b_pp = DTB(hp,wp);
    #undef DTA
    #undef DTC
    #undef DTB
    float A0 = (fabsf(b_pm) - b_pm + fabsf(b00) - b00) * 0.25f;
    float A1 = (c_wm + c00 - fabsf(b_wm) - fabsf(b00)) * 0.5f;
    float A2 = (fabsf(b_mm) + b_mm + fabsf(b00) + b00) * 0.25f;
    float A3 = (a_hp + a00 - fabsf(b_hp) - fabsf(b00)) * 0.5f;
    float A4 = -(a_hp + 2.0f*a00 + a_hm) * 0.5f
               - (fabsf(b_pm) - b_pm + fabsf(b_mm) + b_mm) * 0.25f
               - (fabsf(b_pp) + b_pp + fabsf(b_mp) - b_mp) * 0.25f
               + (fabsf(b_hp) + fabsf(b_hm) + fabsf(b_wp) + fabsf(b_wm) + 2.0f*fabsf(b00)) * 0.5f
               - (c_wp + 2.0f*c00 + c_wm) * 0.5f;
    float A5 = (a_hm + a00 - fabsf(b_hm) - fabsf(b00)) * 0.5f;
    float A6 = (fabsf(b_pp) + b_pp + fabsf(b00) + b00) * 0.25f;
    float A7 = (c_wp + c00 - fabsf(b_wp) - fabsf(b00)) * 0.5f;
    float A8 = (fabsf(b_mp) - b_mp + fabsf(b00) - b00) * 0.25f;

    float inv_dg = 1.0f / dg[p];
    float mhm = (h > 0)      ? 1.0f : 0.0f;
    float mhp = (h < HH - 1) ? 1.0f : 0.0f;
    float mwm = (w > 0)      ? 1.0f : 0.0f;
    float mwp = (w < WW - 1) ? 1.0f : 0.0f;

    g_aux[0*NP+p]  = A0 * inv_dg * mhm * mwm;
    g_aux[1*NP+p]  = A1 * inv_dg * mhm;
    g_aux[2*NP+p]  = A2 * inv_dg * mhm * mwp;
    g_aux[3*NP+p]  = A3 * inv_dg * mwm;
    g_aux[4*NP+p]  = A4 * inv_dg;
    g_aux[5*NP+p]  = A5 * inv_dg * mwp;
    g_aux[6*NP+p]  = A6 * inv_dg * mhp * mwm;
    g_aux[7*NP+p]  = A7 * inv_dg * mhp;
    g_aux[8*NP+p]  = A8 * inv_dg * mhp * mwp;
    g_aux[9*NP+p]  = 0.5f * hinv[p*3+0];  // vx^2 coeff
    g_aux[10*NP+p] = 0.5f * hinv[p*3+1];  // vy^2 coeff
    g_aux[11*NP+p] =        hinv[p*3+2];  // vx*vy coeff (2*b*0.5)
}

// ---- K1: transpose interleaved v -> planar g_a, and compute s0 = logsumexp ----
__global__ void __launch_bounds__(256) k_in(const float* __restrict__ v) {
    int p = blockIdx.x * blockDim.x + threadIdx.x;
    if (p >= NP) return;
    const float4* xp = (const float4*)v + (size_t)p * NQ;
    float4 t[NQ];
    float m = -3.402823466e38f;
    #pragma unroll
    for (int q = 0; q < NQ; q++) {
        t[q] = xp[q];
        m = fmaxf(m, fmaxf(fmaxf(t[q].x, t[q].y), fmaxf(t[q].z, t[q].w)));
    }
    float sum = 0.0f;
    #pragma unroll
    for (int q = 0; q < NQ; q++) {
        sum += __expf(t[q].x - m) + __expf(t[q].y - m)
             + __expf(t[q].z - m) + __expf(t[q].w - m);
        g_a[(q*4+0)*NP + p] = t[q].x;
        g_a[(q*4+1)*NP + p] = t[q].y;
        g_a[(q*4+2)*NP + p] = t[q].z;
        g_a[(q*4+3)*NP + p] = t[q].w;
    }
    g_s0[p] = m + __logf(sum);
}

// ---- K2: fused Euler step on planar data; epilogue computes next-step s
//          into the OTHER s buffer (no intra-launch race).
//          last==1: write interleaved to d_out, skip s. ----
__global__ void __launch_bounds__(128) k_step(int ssel, int last,
                                              float* __restrict__ out_ilv) {
    int p = blockIdx.x * blockDim.x + threadIdx.x;
    if (p >= NP) return;
    const float* x  = (ssel == 1) ? (const float*)g_a : (const float*)g_b;
    float* xo       = (ssel == 1) ? g_b : g_a;
    const float* si = (ssel == 1) ? (const float*)g_s0 : (const float*)g_s1;
    float* so       = (ssel == 1) ? g_s1 : g_s0;

    int h = p >> 9, w = p & 511;
    int hm = (h - 1) & 511, hp = (h + 1) & 511;
    int wm = (w - 1) & 511, wp = (w + 1) & 511;
    int i_mm = (hm << 9) + wm, i_m0 = (hm << 9) + w, i_mp = (hm << 9) + wp;
    int i_0m = (h  << 9) + wm,                       i_0p = (h  << 9) + wp;
    int i_pm = (hp << 9) + wm, i_p0 = (hp << 9) + w, i_pp = (hp << 9) + wp;

    float A0 = g_aux[0*NP+p], A1 = g_aux[1*NP+p], A2 = g_aux[2*NP+p];
    float A3 = g_aux[3*NP+p], A4 = g_aux[4*NP+p], A5 = g_aux[5*NP+p];
    float A6 = g_aux[6*NP+p], A7 = g_aux[7*NP+p], A8 = g_aux[8*NP+p];
    float ha = g_aux[9*NP+p], hb = g_aux[10*NP+p], hc = g_aux[11*NP+p];

    float sc  = si[p];
    float dsx = si[i_p0] - sc;   // periodic roll along H
    float dsy = si[i_0p] - sc;   // periodic roll along W

    float val[NC];
    float cen[NC];
    float vsum = 0.0f;
    #pragma unroll
    for (int c = 0; c < NC; c++) {
        const float* xc = x + (size_t)c * NP;
        float t00 = xc[p];
        float tp0 = xc[i_p0];
        float t0p = xc[i_0p];
        float acc = A4 * t00;
        acc = fmaf(A0, xc[i_mm], acc);
        acc = fmaf(A1, xc[i_m0], acc);
        acc = fmaf(A2, xc[i_mp], acc);
        acc = fmaf(A3, xc[i_0m], acc);
        acc = fmaf(A5, t0p, acc);
        acc = fmaf(A6, xc[i_pm], acc);
        acc = fmaf(A7, tp0, acc);
        acc = fmaf(A8, xc[i_pp], acc);
        float vx = (tp0 - t00) - dsx;
        float vy = (t0p - t00) - dsy;
        acc = fmaf(fmaf(hc, vy, ha * vx), vx, acc);
        acc = fmaf(hb, vy * vy, acc);
        acc = fmaf(0.1f, t00, acc);
        val[c] = acc;
        cen[c] = t00;
        vsum += acc;
    }
    float mean = vsum * (1.0f / 48.0f);

    // updated state xn[c] (reuse val[])
    #pragma unroll
    for (int c = 0; c < NC; c++) {
        float t = val[c] - mean;
        t = fminf(fmaxf(t, -1e8f), 1e8f);
        val[c] = fmaf(0.2f, t, cen[c]);
    }

    if (!last) {
        float m = -3.402823466e38f;
        #pragma unroll
        for (int c = 0; c < NC; c++) m = fmaxf(m, val[c]);
        float sum = 0.0f;
        #pragma unroll
        for (int c = 0; c < NC; c++) {
            sum += __expf(val[c] - m);
            xo[(size_t)c * NP + p] = val[c];
        }
        so[p] = m + __logf(sum);
    } else {
        float4* o = (float4*)out_ilv + (size_t)p * NQ;
        #pragma unroll
        for (int q = 0; q < NQ; q++) {
            float4 oo;
            oo.x = val[q*4+0];
            oo.y = val[q*4+1];
            oo.z = val[q*4+2];
            oo.w = val[q*4+3];
            o[q] = oo;
        }
    }
}

extern "C" void kernel_launch(void* const* d_in, const int* in_sizes, int n_in,
                              void* d_out, int out_size) {
    const float* v    = (const float*)d_in[0];
    const float* Dt   = (const float*)d_in[1];
    const float* dg   = (const float*)d_in[2];
    const float* hinv = (const float*)d_in[3];
    float* out = (float*)d_out;

    k_aux<<<NP / 256, 256>>>(Dt, dg, hinv);
    k_in<<<NP / 256, 256>>>(v);

    // planar ping-pong: g_a/s0 -> g_b/s1 -> g_a/s0 -> g_b/s1 -> g_a/s0 -> out
    k_step<<<NP / 128, 128>>>(1, 0, out);
    k_step<<<NP / 128, 128>>>(2, 0, out);
    k_step<<<NP / 128, 128>>>(1, 0, out);
    k_step<<<NP / 128, 128>>>(2, 0, out);
    k_step<<<NP / 128, 128>>>(1, 1, out);
}

// round 4
// speedup vs baseline: 2.1895x; 2.1895x over previous
#include <cuda_runtime.h>

#define HH 512
#define WW 512
#define NC 48
#define NP (HH*WW)
#define NQ 12
#define CPT 12   // channels per thread
#define GPP 4    // channel-groups (threads) per pixel
#define PXB 64   // pixels per block

// ---- scratch (static device globals: allocation-free, graph-safe) ----
__device__ float g_a[NC*NP];
__device__ float g_b[NC*NP];
__device__ float g_s0[NP];
__device__ float g_s1[NP];
__device__ float g_aux[12*NP];

// ---- K0: per-pixel stencil weights (periodic rolls on Dt), folded /dg, 0.5*hinv,
//          zero-pad masks; planar output ----
__global__ void k_aux(const float* __restrict__ Dt, const float* __restrict__ dg,
                      const float* __restrict__ hinv) {
    int p = blockIdx.x * blockDim.x + threadIdx.x;
    if (p >= NP) return;
    int h = p >> 9, w = p & 511;
    int hm = (h - 1) & 511, hp = (h + 1) & 511;
    int wm = (w - 1) & 511, wp = (w + 1) & 511;
    #define DTA(hh,ww) Dt[(((hh)<<9)+(ww))*3+0]
    #define DTC(hh,ww) Dt[(((hh)<<9)+(ww))*3+1]
    #define DTB(hh,ww) Dt[(((hh)<<9)+(ww))*3+2]
    float a00 = DTA(h,w),  c00 = DTC(h,w),  b00 = DTB(h,w);
    float a_hm = DTA(hm,w), b_hm = DTB(hm,w);
    float a_hp = DTA(hp,w), b_hp = DTB(hp,w);
    float c_wm = DTC(h,wm), b_wm = DTB(h,wm);
    float c_wp = DTC(h,wp), b_wp = DTB(h,wp);
    float b_mm = DTB(hm,wm);
    float b_mp = DTB(hm,wp);
    float b_pm = DTB(hp,wm);
    float b_pp = DTB(hp,wp);
    #undef DTA
    #undef DTC
    #undef DTB
    float A0 = (fabsf(b_pm) - b_pm + fabsf(b00) - b00) * 0.25f;
    float A1 = (c_wm + c00 - fabsf(b_wm) - fabsf(b00)) * 0.5f;
    float A2 = (fabsf(b_mm) + b_mm + fabsf(b00) + b00) * 0.25f;
    float A3 = (a_hp + a00 - fabsf(b_hp) - fabsf(b00)) * 0.5f;
    float A4 = -(a_hp + 2.0f*a00 + a_hm) * 0.5f
               - (fabsf(b_pm) - b_pm + fabsf(b_mm) + b_mm) * 0.25f
               - (fabsf(b_pp) + b_pp + fabsf(b_mp) - b_mp) * 0.25f
               + (fabsf(b_hp) + fabsf(b_hm) + fabsf(b_wp) + fabsf(b_wm) + 2.0f*fabsf(b00)) * 0.5f
               - (c_wp + 2.0f*c00 + c_wm) * 0.5f;
    float A5 = (a_hm + a00 - fabsf(b_hm) - fabsf(b00)) * 0.5f;
    float A6 = (fabsf(b_pp) + b_pp + fabsf(b00) + b00) * 0.25f;
    float A7 = (c_wp + c00 - fabsf(b_wp) - fabsf(b00)) * 0.5f;
    float A8 = (fabsf(b_mp) - b_mp + fabsf(b00) - b00) * 0.25f;

    float inv_dg = 1.0f / dg[p];
    float mhm = (h > 0)      ? 1.0f : 0.0f;
    float mhp = (h < HH - 1) ? 1.0f : 0.0f;
    float mwm = (w > 0)      ? 1.0f : 0.0f;
    float mwp = (w < WW - 1) ? 1.0f : 0.0f;

    g_aux[0*NP+p]  = A0 * inv_dg * mhm * mwm;
    g_aux[1*NP+p]  = A1 * inv_dg * mhm;
    g_aux[2*NP+p]  = A2 * inv_dg * mhm * mwp;
    g_aux[3*NP+p]  = A3 * inv_dg * mwm;
    g_aux[4*NP+p]  = A4 * inv_dg;
    g_aux[5*NP+p]  = A5 * inv_dg * mwp;
    g_aux[6*NP+p]  = A6 * inv_dg * mhp * mwm;
    g_aux[7*NP+p]  = A7 * inv_dg * mhp;
    g_aux[8*NP+p]  = A8 * inv_dg * mhp * mwp;
    g_aux[9*NP+p]  = 0.5f * hinv[p*3+0];
    g_aux[10*NP+p] = 0.5f * hinv[p*3+1];
    g_aux[11*NP+p] =        hinv[p*3+2];
}

// ---- K1: transpose interleaved v -> planar g_a, compute s0 = logsumexp ----
__global__ void __launch_bounds__(256) k_in(const float* __restrict__ v) {
    int p = blockIdx.x * blockDim.x + threadIdx.x;
    if (p >= NP) return;
    const float4* xp = (const float4*)v + (size_t)p * NQ;
    float4 t[NQ];
    float m = -3.402823466e38f;
    #pragma unroll
    for (int q = 0; q < NQ; q++) {
        t[q] = xp[q];
        m = fmaxf(m, fmaxf(fmaxf(t[q].x, t[q].y), fmaxf(t[q].z, t[q].w)));
    }
    float sum = 0.0f;
    #pragma unroll
    for (int q = 0; q < NQ; q++) {
        sum += __expf(t[q].x - m) + __expf(t[q].y - m)
             + __expf(t[q].z - m) + __expf(t[q].w - m);
        g_a[(q*4+0)*NP + p] = t[q].x;
        g_a[(q*4+1)*NP + p] = t[q].y;
        g_a[(q*4+2)*NP + p] = t[q].z;
        g_a[(q*4+3)*NP + p] = t[q].w;
    }
    g_s0[p] = m + __logf(sum);
}

// ---- K2: fused Euler step; 4 threads per pixel, 12 channels each.
//          Channel reductions (mean / max / expsum) via smem 4-way. ----
__global__ void __launch_bounds__(PXB*GPP) k_step(int ssel, int last,
                                                  float* __restrict__ out_ilv) {
    __shared__ float red0[GPP][PXB];
    __shared__ float red1[GPP][PXB];
    __shared__ float red2[GPP][PXB];

    int tx = threadIdx.x;           // pixel within block
    int ty = threadIdx.y;           // channel group
    int p  = blockIdx.x * PXB + tx;
    int c0 = ty * CPT;

    const float* x  = (ssel == 1) ? (const float*)g_a : (const float*)g_b;
    float* xo       = (ssel == 1) ? g_b : g_a;
    const float* si = (ssel == 1) ? (const float*)g_s0 : (const float*)g_s1;
    float* so       = (ssel == 1) ? g_s1 : g_s0;

    int h = p >> 9, w = p & 511;
    int hm = (h - 1) & 511, hp = (h + 1) & 511;
    int wm = (w - 1) & 511, wp = (w + 1) & 511;
    int i_mm = (hm << 9) + wm, i_m0 = (hm << 9) + w, i_mp = (hm << 9) + wp;
    int i_0m = (h  << 9) + wm,                       i_0p = (h  << 9) + wp;
    int i_pm = (hp << 9) + wm, i_p0 = (hp << 9) + w, i_pp = (hp << 9) + wp;

    float A0 = g_aux[0*NP+p], A1 = g_aux[1*NP+p], A2 = g_aux[2*NP+p];
    float A3 = g_aux[3*NP+p], A4 = g_aux[4*NP+p], A5 = g_aux[5*NP+p];
    float A6 = g_aux[6*NP+p], A7 = g_aux[7*NP+p], A8 = g_aux[8*NP+p];
    float ha = g_aux[9*NP+p], hb = g_aux[10*NP+p], hc = g_aux[11*NP+p];

    float sc  = si[p];
    float dsx = si[i_p0] - sc;
    float dsy = si[i_0p] - sc;

    float val[CPT];
    float cen[CPT];
    float vsum = 0.0f;
    #pragma unroll
    for (int c = 0; c < CPT; c++) {
        const float* xc = x + (size_t)(c0 + c) * NP;
        float t00 = xc[p];
        float tp0 = xc[i_p0];
        float t0p = xc[i_0p];
        float acc = A4 * t00;
        acc = fmaf(A0, xc[i_mm], acc);
        acc = fmaf(A1, xc[i_m0], acc);
        acc = fmaf(A2, xc[i_mp], acc);
        acc = fmaf(A3, xc[i_0m], acc);
        acc = fmaf(A5, t0p, acc);
        acc = fmaf(A6, xc[i_pm], acc);
        acc = fmaf(A7, tp0, acc);
        acc = fmaf(A8, xc[i_pp], acc);
        float vx = (tp0 - t00) - dsx;
        float vy = (t0p - t00) - dsy;
        acc = fmaf(fmaf(hc, vy, ha * vx), vx, acc);
        acc = fmaf(hb, vy * vy, acc);
        acc = fmaf(0.1f, t00, acc);
        val[c] = acc;
        cen[c] = t00;
        vsum += acc;
    }

    // 4-way mean reduction
    red0[ty][tx] = vsum;
    __syncthreads();
    float mean = (red0[0][tx] + red0[1][tx] + red0[2][tx] + red0[3][tx]) * (1.0f / 48.0f);

    // Euler update
    #pragma unroll
    for (int c = 0; c < CPT; c++) {
        float t = val[c] - mean;
        t = fminf(fmaxf(t, -1e8f), 1e8f);
        val[c] = fmaf(0.2f, t, cen[c]);
    }

    if (!last) {
        // store planar + fused next-step logsumexp
        float m12 = val[0];
        #pragma unroll
        for (int c = 1; c < CPT; c++) m12 = fmaxf(m12, val[c]);
        red1[ty][tx] = m12;
        #pragma unroll
        for (int c = 0; c < CPT; c++)
            xo[(size_t)(c0 + c) * NP + p] = val[c];
        __syncthreads();
        float m = fmaxf(fmaxf(red1[0][tx], red1[1][tx]), fmaxf(red1[2][tx], red1[3][tx]));
        float es = 0.0f;
        #pragma unroll
        for (int c = 0; c < CPT; c++) es += __expf(val[c] - m);
        red2[ty][tx] = es;
        __syncthreads();
        if (ty == 0) {
            float sum = red2[0][tx] + red2[1][tx] + red2[2][tx] + red2[3][tx];
            so[p] = m + __logf(sum);
        }
    } else {
        // interleaved output: 12 contiguous floats at out[p*48 + c0]
        float4* o = (float4*)(out_ilv + (size_t)p * NC + c0);
        #pragma unroll
        for (int q = 0; q < 3; q++) {
            float4 oo;
            oo.x = val[q*4+0];
            oo.y = val[q*4+1];
            oo.z = val[q*4+2];
            oo.w = val[q*4+3];
            o[q] = oo;
        }
    }
}

extern "C" void kernel_launch(void* const* d_in, const int* in_sizes, int n_in,
                              void* d_out, int out_size) {
    const float* v    = (const float*)d_in[0];
    const float* Dt   = (const float*)d_in[1];
    const float* dg   = (const float*)d_in[2];
    const float* hinv = (const float*)d_in[3];
    float* out = (float*)d_out;

    k_aux<<<NP / 256, 256>>>(Dt, dg, hinv);
    k_in<<<NP / 256, 256>>>(v);

    dim3 blk(PXB, GPP);
    int grid = NP / PXB;
    k_step<<<grid, blk>>>(1, 0, out);
    k_step<<<grid, blk>>>(2, 0, out);
    k_step<<<grid, blk>>>(1, 0, out);
    k_step<<<grid, blk>>>(2, 0, out);
    k_step<<<grid, blk>>>(1, 1, out);
}

// round 5
// speedup vs baseline: 2.2065x; 1.0078x over previous
#include <cuda_runtime.h>

#define HH 512
#define WW 512
#define NC 48
#define NP (HH*WW)
#define NQ 12
#define CPT 6    // channels per thread
#define GPP 8    // channel-groups (threads) per pixel
#define PXB 32   // pixels per block (one warp-row)

// ---- scratch (static device globals: allocation-free, graph-safe) ----
__device__ float  g_a[NC*NP];
__device__ float  g_b[NC*NP];
__device__ float  g_s0[NP];
__device__ float  g_s1[NP];
__device__ float4 g_aux4[3*NP];   // 3 planar float4 coeff planes:
                                  // [0]=A0..A3, [1]=A4..A7, [2]=(A8,ha,hb,hc)

// ---- K0: per-pixel stencil weights (periodic rolls on Dt), folded /dg, 0.5*hinv,
//          zero-pad masks; packed float4 planar output ----
__global__ void k_aux(const float* __restrict__ Dt, const float* __restrict__ dg,
                      const float* __restrict__ hinv) {
    int p = blockIdx.x * blockDim.x + threadIdx.x;
    if (p >= NP) return;
    int h = p >> 9, w = p & 511;
    int hm = (h - 1) & 511, hp = (h + 1) & 511;
    int wm = (w - 1) & 511, wp = (w + 1) & 511;
    #define DTA(hh,ww) Dt[(((hh)<<9)+(ww))*3+0]
    #define DTC(hh,ww) Dt[(((hh)<<9)+(ww))*3+1]
    #define DTB(hh,ww) Dt[(((hh)<<9)+(ww))*3+2]
    float a00 = DTA(h,w),  c00 = DTC(h,w),  b00 = DTB(h,w);
    float a_hm = DTA(hm,w), b_hm = DTB(hm,w);
    float a_hp = DTA(hp,w), b_hp = DTB(hp,w);
    float c_wm = DTC(h,wm), b_wm = DTB(h,wm);
    float c_wp = DTC(h,wp), b_wp = DTB(h,wp);
    float b_mm = DTB(hm,wm);
    float b_mp = DTB(hm,wp);
    float b_pm = DTB(hp,wm);
    float b_pp = DTB(hp,wp);
    #undef DTA
    #undef DTC
    #undef DTB
    float A0 = (fabsf(b_pm) - b_pm + fabsf(b00) - b00) * 0.25f;
    float A1 = (c_wm + c00 - fabsf(b_wm) - fabsf(b00)) * 0.5f;
    float A2 = (fabsf(b_mm) + b_mm + fabsf(b00) + b00) * 0.25f;
    float A3 = (a_hp + a00 - fabsf(b_hp) - fabsf(b00)) * 0.5f;
    float A4 = -(a_hp + 2.0f*a00 + a_hm) * 0.5f
               - (fabsf(b_pm) - b_pm + fabsf(b_mm) + b_mm) * 0.25f
               - (fabsf(b_pp) + b_pp + fabsf(b_mp) - b_mp) * 0.25f
               + (fabsf(b_hp) + fabsf(b_hm) + fabsf(b_wp) + fabsf(b_wm) + 2.0f*fabsf(b00)) * 0.5f
               - (c_wp + 2.0f*c00 + c_wm) * 0.5f;
    float A5 = (a_hm + a00 - fabsf(b_hm) - fabsf(b00)) * 0.5f;
    float A6 = (fabsf(b_pp) + b_pp + fabsf(b00) + b00) * 0.25f;
    float A7 = (c_wp + c00 - fabsf(b_wp) - fabsf(b00)) * 0.5f;
    float A8 = (fabsf(b_mp) - b_mp + fabsf(b00) - b00) * 0.25f;

    float inv_dg = 1.0f / dg[p];
    float mhm = (h > 0)      ? 1.0f : 0.0f;
    float mhp = (h < HH - 1) ? 1.0f : 0.0f;
    float mwm = (w > 0)      ? 1.0f : 0.0f;
    float mwp = (w < WW - 1) ? 1.0f : 0.0f;

    float4 q0, q1, q2;
    q0.x = A0 * inv_dg * mhm * mwm;
    q0.y = A1 * inv_dg * mhm;
    q0.z = A2 * inv_dg * mhm * mwp;
    q0.w = A3 * inv_dg * mwm;
    q1.x = A4 * inv_dg;
    q1.y = A5 * inv_dg * mwp;
    q1.z = A6 * inv_dg * mhp * mwm;
    q1.w = A7 * inv_dg * mhp;
    q2.x = A8 * inv_dg * mhp * mwp;
    q2.y = 0.5f * hinv[p*3+0];
    q2.z = 0.5f * hinv[p*3+1];
    q2.w =        hinv[p*3+2];
    g_aux4[p]        = q0;
    g_aux4[NP + p]   = q1;
    g_aux4[2*NP + p] = q2;
}

// ---- K1: transpose interleaved v -> planar g_a, compute s0 = logsumexp ----
__global__ void __launch_bounds__(256) k_in(const float* __restrict__ v) {
    int p = blockIdx.x * blockDim.x + threadIdx.x;
    if (p >= NP) return;
    const float4* xp = (const float4*)v + (size_t)p * NQ;
    float4 t[NQ];
    float m = -3.402823466e38f;
    #pragma unroll
    for (int q = 0; q < NQ; q++) {
        t[q] = xp[q];
        m = fmaxf(m, fmaxf(fmaxf(t[q].x, t[q].y), fmaxf(t[q].z, t[q].w)));
    }
    float sum = 0.0f;
    #pragma unroll
    for (int q = 0; q < NQ; q++) {
        sum += __expf(t[q].x - m) + __expf(t[q].y - m)
             + __expf(t[q].z - m) + __expf(t[q].w - m);
        g_a[(q*4+0)*NP + p] = t[q].x;
        g_a[(q*4+1)*NP + p] = t[q].y;
        g_a[(q*4+2)*NP + p] = t[q].z;
        g_a[(q*4+3)*NP + p] = t[q].w;
    }
    g_s0[p] = m + __logf(sum);
}

// ---- K2: fused Euler step; 8 threads per pixel, 6 channels each. ----
__global__ void __launch_bounds__(PXB*GPP, 5) k_step(int ssel, int last,
                                                     float* __restrict__ out_ilv) {
    __shared__ float red0[GPP][PXB];
    __shared__ float red1[GPP][PXB];
    __shared__ float red2[GPP][PXB];

    int tx = threadIdx.x;           // pixel within block (0..31)
    int ty = threadIdx.y;           // channel group (0..7)
    int p  = blockIdx.x * PXB + tx;
    int c0 = ty * CPT;

    const float* x  = (ssel == 1) ? (const float*)g_a : (const float*)g_b;
    float* xo       = (ssel == 1) ? g_b : g_a;
    const float* si = (ssel == 1) ? (const float*)g_s0 : (const float*)g_s1;
    float* so       = (ssel == 1) ? g_s1 : g_s0;

    int h = p >> 9, w = p & 511;
    int hm = (h - 1) & 511, hp = (h + 1) & 511;
    int wm = (w - 1) & 511, wp = (w + 1) & 511;
    int i_mm = (hm << 9) + wm, i_m0 = (hm << 9) + w, i_mp = (hm << 9) + wp;
    int i_0m = (h  << 9) + wm,                       i_0p = (h  << 9) + wp;
    int i_pm = (hp << 9) + wm, i_p0 = (hp << 9) + w, i_pp = (hp << 9) + wp;

    float4 q0 = g_aux4[p];
    float4 q1 = g_aux4[NP + p];
    float4 q2 = g_aux4[2*NP + p];
    float A0 = q0.x, A1 = q0.y, A2 = q0.z, A3 = q0.w;
    float A4 = q1.x, A5 = q1.y, A6 = q1.z, A7 = q1.w;
    float A8 = q2.x, ha = q2.y, hb = q2.z, hc = q2.w;

    float sc  = si[p];
    float dsx = si[i_p0] - sc;
    float dsy = si[i_0p] - sc;

    float val[CPT];
    float cen[CPT];
    float vsum = 0.0f;
    #pragma unroll
    for (int c = 0; c < CPT; c++) {
        const float* xc = x + (size_t)(c0 + c) * NP;
        float t00 = xc[p];
        float tp0 = xc[i_p0];
        float t0p = xc[i_0p];
        float acc = A4 * t00;
        acc = fmaf(A0, xc[i_mm], acc);
        acc = fmaf(A1, xc[i_m0], acc);
        acc = fmaf(A2, xc[i_mp], acc);
        acc = fmaf(A3, xc[i_0m], acc);
        acc = fmaf(A5, t0p, acc);
        acc = fmaf(A6, xc[i_pm], acc);
        acc = fmaf(A7, tp0, acc);
        acc = fmaf(A8, xc[i_pp], acc);
        float vx = (tp0 - t00) - dsx;
        float vy = (t0p - t00) - dsy;
        acc = fmaf(fmaf(hc, vy, ha * vx), vx, acc);
        acc = fmaf(hb, vy * vy, acc);
        acc = fmaf(0.1f, t00, acc);
        val[c] = acc;
        cen[c] = t00;
        vsum += acc;
    }

    // 8-way mean reduction
    red0[ty][tx] = vsum;
    __syncthreads();
    float mean = 0.0f;
    #pragma unroll
    for (int g = 0; g < GPP; g++) mean += red0[g][tx];
    mean *= (1.0f / 48.0f);

    // Euler update
    #pragma unroll
    for (int c = 0; c < CPT; c++) {
        float t = val[c] - mean;
        t = fminf(fmaxf(t, -1e8f), 1e8f);
        val[c] = fmaf(0.2f, t, cen[c]);
    }

    if (!last) {
        float mloc = val[0];
        #pragma unroll
        for (int c = 1; c < CPT; c++) mloc = fmaxf(mloc, val[c]);
        red1[ty][tx] = mloc;
        #pragma unroll
        for (int c = 0; c < CPT; c++)
            xo[(size_t)(c0 + c) * NP + p] = val[c];
        __syncthreads();
        float m = red1[0][tx];
        #pragma unroll
        for (int g = 1; g < GPP; g++) m = fmaxf(m, red1[g][tx]);
        float es = 0.0f;
        #pragma unroll
        for (int c = 0; c < CPT; c++) es += __expf(val[c] - m);
        red2[ty][tx] = es;
        __syncthreads();
        if (ty == 0) {
            float sum = 0.0f;
            #pragma unroll
            for (int g = 0; g < GPP; g++) sum += red2[g][tx];
            so[p] = m + __logf(sum);
        }
    } else {
        // interleaved output: 6 contiguous floats at out[p*48 + c0] (8B aligned)
        float2* o = (float2*)(out_ilv + (size_t)p * NC + c0);
        #pragma unroll
        for (int q = 0; q < 3; q++) {
            float2 oo;
            oo.x = val[q*2+0];
            oo.y = val[q*2+1];
            o[q] = oo;
        }
    }
}

extern "C" void kernel_launch(void* const* d_in, const int* in_sizes, int n_in,
                              void* d_out, int out_size) {
    const float* v    = (const float*)d_in[0];
    const float* Dt   = (const float*)d_in[1];
    const float* dg   = (const float*)d_in[2];
    const float* hinv = (const float*)d_in[3];
    float* out = (float*)d_out;

    k_aux<<<NP / 256, 256>>>(Dt, dg, hinv);
    k_in<<<NP / 256, 256>>>(v);

    dim3 blk(PXB, GPP);
    int grid = NP / PXB;
    k_step<<<grid, blk>>>(1, 0, out);
    k_step<<<grid, blk>>>(2, 0, out);
    k_step<<<grid, blk>>>(1, 0, out);
    k_step<<<grid, blk>>>(2, 0, out);
    k_step<<<grid, blk>>>(1, 1, out);
}